// round 6
// baseline (speedup 1.0000x reference)
#include <cuda_runtime.h>
#include <cuda_bf16.h>
#include <cstdint>

#define T_TOK 4096   // B*S
#define DD    1024   // model dim
#define EE    8      // experts
#define II    1408   // ffn dim

// ---------------------------------------------------------------------------
// Static device scratch
// ---------------------------------------------------------------------------
__device__ int   g_count[EE];
__device__ int   g_tok [EE * T_TOK];
__device__ float g_prob[EE * T_TOK];
__device__ int4  g_rec [T_TOK];
__device__ __align__(16) __nv_bfloat16 g_Xhi[(size_t)T_TOK * DD];
__device__ __align__(16) __nv_bfloat16 g_Xlo[(size_t)T_TOK * DD];
__device__ __align__(16) __nv_bfloat16 g_Wgh[(size_t)EE * II * DD];
__device__ __align__(16) __nv_bfloat16 g_Wgl[(size_t)EE * II * DD];
__device__ __align__(16) __nv_bfloat16 g_Wuh[(size_t)EE * II * DD];
__device__ __align__(16) __nv_bfloat16 g_Wul[(size_t)EE * II * DD];
__device__ __align__(16) __nv_bfloat16 g_Wdh[(size_t)EE * DD * II];
__device__ __align__(16) __nv_bfloat16 g_Wdl[(size_t)EE * DD * II];
__device__ __align__(16) __nv_bfloat16 g_Hhi[(size_t)EE * T_TOK * II];
__device__ __align__(16) __nv_bfloat16 g_Hlo[(size_t)EE * T_TOK * II];
__device__ __align__(16) float         g_Yp [(size_t)EE * T_TOK * DD];

// ---------------------------------------------------------------------------
// PTX helpers (sm_80-era ISA: compiles under plain compute_100 target)
// ---------------------------------------------------------------------------
__device__ __forceinline__ uint32_t smem_u32(const void* p) {
    uint32_t a;
    asm("{ .reg .u64 t; cvta.to.shared.u64 t, %1; cvt.u32.u64 %0, t; }" : "=r"(a) : "l"(p));
    return a;
}

#define CP_ASYNC16(dst, src) \
    asm volatile("cp.async.cg.shared.global [%0], [%1], 16;" :: "r"(dst), "l"(src))
#define CP_COMMIT() asm volatile("cp.async.commit_group;")
#define CP_WAIT0()  asm volatile("cp.async.wait_group 0;")
#define CP_WAIT1()  asm volatile("cp.async.wait_group 1;")

#define LDSM_X4(r0, r1, r2, r3, addr) \
    asm volatile("ldmatrix.sync.aligned.m8n8.x4.shared.b16 {%0,%1,%2,%3}, [%4];" \
        : "=r"(r0), "=r"(r1), "=r"(r2), "=r"(r3) : "r"(addr))

#define MMA16816(d, a, b) \
    asm volatile("mma.sync.aligned.m16n8k16.row.col.f32.bf16.bf16.f32 " \
        "{%0,%1,%2,%3}, {%4,%5,%6,%7}, {%8,%9}, {%0,%1,%2,%3};" \
        : "+f"((d)[0]), "+f"((d)[1]), "+f"((d)[2]), "+f"((d)[3]) \
        : "r"((a)[0]), "r"((a)[1]), "r"((a)[2]), "r"((a)[3]), "r"((b)[0]), "r"((b)[1]))

// 80B-padded rows -> conflict-free ldmatrix
#define ROW_B    80
#define MAT_A_B  (128 * ROW_B)    // 10240 B : 128x32 bf16 matrix
#define MAT_B_B  (64 * ROW_B)     // 5120 B  : 64x32 bf16 matrix

// GEMM1 (fused gate+up): stage = Ahi, Alo (128x32) + Bgh, Bgl, Buh, Bul (64x32)
#define G1_STAGE (2 * MAT_A_B + 4 * MAT_B_B)   // 40960
#define G1_SMEM  (1024 + 2 * G1_STAGE)         // 82944
// GEMM2: stage = Ahi, Alo, Bhi, Blo (128x32 each)
#define G2_STAGE (4 * MAT_A_B)                 // 40960
#define G2_SMEM  (1024 + 2 * G2_STAGE)         // 82944

// ---------------------------------------------------------------------------
// 0) reset counters
// ---------------------------------------------------------------------------
__global__ void zero_counts_kernel() {
    if (threadIdx.x < EE) g_count[threadIdx.x] = 0;
}

// ---------------------------------------------------------------------------
// 1) router (verified at 1.15e-6)
// ---------------------------------------------------------------------------
__global__ __launch_bounds__(256) void router_kernel(
    const float* __restrict__ x, const float* __restrict__ gate_w)
{
    __shared__ float sx[DD];
    __shared__ float sc[EE];
    const int t = blockIdx.x, tid = threadIdx.x;
    ((float4*)sx)[tid] = ((const float4*)(x + (size_t)t * DD))[tid];
    __syncthreads();
    const int w = tid >> 5, lane = tid & 31;
    const float* gw = gate_w + w * DD;
    float s = 0.f;
    #pragma unroll 8
    for (int j = lane; j < DD; j += 32) s += sx[j] * gw[j];
    #pragma unroll
    for (int o = 16; o > 0; o >>= 1) s += __shfl_down_sync(0xFFFFFFFFu, s, o);
    if (lane == 0) sc[w] = s;
    __syncthreads();
    if (tid == 0) {
        int e0 = 0; float s0 = sc[0];
        #pragma unroll
        for (int e = 1; e < EE; e++) if (sc[e] > s0) { s0 = sc[e]; e0 = e; }
        int e1 = -1; float s1 = -3.0e38f;
        #pragma unroll
        for (int e = 0; e < EE; e++) if (e != e0 && sc[e] > s1) { s1 = sc[e]; e1 = e; }
        float z = expf(s1 - s0);
        float p1 = z / (1.f + z);
        float p0 = 1.f - p1;
        int sl0 = atomicAdd(&g_count[e0], 1);
        int sl1 = atomicAdd(&g_count[e1], 1);
        g_tok [e0 * T_TOK + sl0] = t;  g_prob[e0 * T_TOK + sl0] = p0;
        g_tok [e1 * T_TOK + sl1] = t;  g_prob[e1 * T_TOK + sl1] = p1;
        g_rec[t] = make_int4(e0, sl0, e1, sl1);
    }
}

// ---------------------------------------------------------------------------
// 2) fp32 -> (bf16 hi, bf16 lo) split
// ---------------------------------------------------------------------------
__global__ __launch_bounds__(256) void split_kernel(const float* __restrict__ s, int which, int n4)
{
    int i = blockIdx.x * 256 + threadIdx.x;
    if (i >= n4) return;
    __nv_bfloat16 *hi, *lo;
    switch (which) {
        case 0:  hi = g_Xhi; lo = g_Xlo; break;
        case 1:  hi = g_Wgh; lo = g_Wgl; break;
        case 2:  hi = g_Wuh; lo = g_Wul; break;
        default: hi = g_Wdh; lo = g_Wdl; break;
    }
    float4 v = ((const float4*)s)[i];
    float vv[4] = {v.x, v.y, v.z, v.w};
    unsigned short h[4], l[4];
    #pragma unroll
    for (int j = 0; j < 4; j++) {
        __nv_bfloat16 a = __float2bfloat16(vv[j]);
        __nv_bfloat16 b = __float2bfloat16(vv[j] - __bfloat162float(a));
        h[j] = __bfloat16_as_ushort(a);
        l[j] = __bfloat16_as_ushort(b);
    }
    *(ushort4*)(hi + 4 * (size_t)i) = make_ushort4(h[0], h[1], h[2], h[3]);
    *(ushort4*)(lo + 4 * (size_t)i) = make_ushort4(l[0], l[1], l[2], l[3]);
}

// ---------------------------------------------------------------------------
// 3) GEMM1 fused: 128(M) x 64(N) tile, gate AND up, silu epilogue -> H hi/lo
//    8 warps: warp_m = wid&3 (32 rows), warp_n = wid>>2 (32 cols)
// ---------------------------------------------------------------------------
__global__ __launch_bounds__(256) void gemm1_fused()
{
    extern __shared__ char smem[];
    const int e   = blockIdx.z;
    const int cnt = g_count[e];
    const int m0  = blockIdx.y * 128;
    if (m0 >= cnt) return;
    const int n0  = blockIdx.x * 64;
    const int tid = threadIdx.x;
    const int wid = tid >> 5, lane = tid & 31;
    const int warp_m = wid & 3;
    const int warp_n = wid >> 2;

    int* s_tok = (int*)smem;
    const uint32_t sd = smem_u32(smem + 1024);

    if (tid < 128) {
        int m = m0 + tid;
        s_tok[tid] = g_tok[e * T_TOK + (m < cnt ? m : cnt - 1)];
    }
    __syncthreads();

    const size_t wb = (size_t)e * II * DD + (size_t)n0 * DD;
    const __nv_bfloat16* Bg[2] = { g_Wgh + wb, g_Wgl + wb };
    const __nv_bfloat16* Bu[2] = { g_Wuh + wb, g_Wul + wb };

    auto load_stage = [&](int buf, int kt) {
        const int k0 = kt * 32;
        const uint32_t sbase = sd + buf * G1_STAGE;
        #pragma unroll
        for (int i = 0; i < 8; i++) {
            const int idx = tid + 256 * i;
            uint32_t dst;
            const __nv_bfloat16* src;
            if (idx < 1024) {                    // A: Ahi(512), Alo(512)
                const int mat = idx >> 9;
                const int c   = idx & 511;
                const int row = c >> 2, kc = c & 3;
                dst = sbase + mat * MAT_A_B + row * ROW_B + kc * 16;
                src = (mat == 0 ? g_Xhi : g_Xlo) + (size_t)s_tok[row] * DD + k0 + kc * 8;
            } else {                             // B: gh, gl, uh, ul (256 each)
                const int idx2 = idx - 1024;
                const int mat = idx2 >> 8;       // 0:gh 1:gl 2:uh 3:ul
                const int c   = idx2 & 255;
                const int row = c >> 2, kc = c & 3;
                dst = sbase + 2 * MAT_A_B + mat * MAT_B_B + row * ROW_B + kc * 16;
                const __nv_bfloat16* base = (mat < 2) ? Bg[mat] : Bu[mat - 2];
                src = base + (size_t)row * DD + k0 + kc * 8;
            }
            CP_ASYNC16(dst, src);
        }
    };

    float accg[2][4][4] = {}, accu[2][4][4] = {};

    load_stage(0, 0);
    CP_COMMIT();
    int buf = 0;

    constexpr int NK = DD / 32;
    for (int kt = 0; kt < NK; kt++) {
        if (kt + 1 < NK) {
            load_stage(buf ^ 1, kt + 1);
            CP_COMMIT();
            CP_WAIT1();
        } else {
            CP_WAIT0();
        }
        __syncthreads();

        const uint32_t ah_b = sd + buf * G1_STAGE + 0 * MAT_A_B;
        const uint32_t al_b = sd + buf * G1_STAGE + 1 * MAT_A_B;
        const uint32_t bgh_b = sd + buf * G1_STAGE + 2 * MAT_A_B + 0 * MAT_B_B;
        const uint32_t bgl_b = sd + buf * G1_STAGE + 2 * MAT_A_B + 1 * MAT_B_B;
        const uint32_t buh_b = sd + buf * G1_STAGE + 2 * MAT_A_B + 2 * MAT_B_B;
        const uint32_t bul_b = sd + buf * G1_STAGE + 2 * MAT_A_B + 3 * MAT_B_B;

        #pragma unroll
        for (int k16 = 0; k16 < 2; k16++) {
            uint32_t ah[2][4], al[2][4];
            const uint32_t acol = (k16 * 16 + (lane >> 4) * 8) * 2;
            #pragma unroll
            for (int mf = 0; mf < 2; mf++) {
                const uint32_t ao = (warp_m * 32 + mf * 16 + (lane & 15)) * ROW_B + acol;
                LDSM_X4(ah[mf][0], ah[mf][1], ah[mf][2], ah[mf][3], ah_b + ao);
                LDSM_X4(al[mf][0], al[mf][1], al[mf][2], al[mf][3], al_b + ao);
            }
            const uint32_t bcol = (k16 * 16 + ((lane >> 3) & 1) * 8) * 2;
            uint32_t gh[4][2], gl[4][2], uh[4][2], ul[4][2];
            #pragma unroll
            for (int nh = 0; nh < 2; nh++) {
                const uint32_t bo = (warp_n * 32 + nh * 16 + (lane >> 4) * 8 + (lane & 7)) * ROW_B + bcol;
                uint32_t r0, r1, r2, r3;
                LDSM_X4(r0, r1, r2, r3, bgh_b + bo);
                gh[nh*2][0]=r0; gh[nh*2][1]=r1; gh[nh*2+1][0]=r2; gh[nh*2+1][1]=r3;
                LDSM_X4(r0, r1, r2, r3, bgl_b + bo);
                gl[nh*2][0]=r0; gl[nh*2][1]=r1; gl[nh*2+1][0]=r2; gl[nh*2+1][1]=r3;
                LDSM_X4(r0, r1, r2, r3, buh_b + bo);
                uh[nh*2][0]=r0; uh[nh*2][1]=r1; uh[nh*2+1][0]=r2; uh[nh*2+1][1]=r3;
                LDSM_X4(r0, r1, r2, r3, bul_b + bo);
                ul[nh*2][0]=r0; ul[nh*2][1]=r1; ul[nh*2+1][0]=r2; ul[nh*2+1][1]=r3;
            }
            #pragma unroll
            for (int mf = 0; mf < 2; mf++) {
                #pragma unroll
                for (int nf = 0; nf < 4; nf++) {
                    MMA16816(accg[mf][nf], ah[mf], gh[nf]);
                    MMA16816(accg[mf][nf], ah[mf], gl[nf]);
                    MMA16816(accg[mf][nf], al[mf], gh[nf]);
                    MMA16816(accu[mf][nf], ah[mf], uh[nf]);
                    MMA16816(accu[mf][nf], ah[mf], ul[nf]);
                    MMA16816(accu[mf][nf], al[mf], uh[nf]);
                }
            }
        }
        __syncthreads();
        buf ^= 1;
    }

    // ---- fused silu epilogue: stage bf16 hi/lo in smem, coalesced store ----
    __nv_bfloat16* sH = (__nv_bfloat16*)(smem + 1024);
    __nv_bfloat16* sL = sH + 128 * 64;
    #pragma unroll
    for (int mf = 0; mf < 2; mf++) {
        const int r0 = warp_m * 32 + mf * 16 + (lane >> 2);
        const int r1 = r0 + 8;
        const float p0 = (m0 + r0 < cnt) ? g_prob[e * T_TOK + m0 + r0] : 0.f;
        const float p1 = (m0 + r1 < cnt) ? g_prob[e * T_TOK + m0 + r1] : 0.f;
        #pragma unroll
        for (int nf = 0; nf < 4; nf++) {
            const int col = warp_n * 32 + nf * 8 + (lane & 3) * 2;
            #pragma unroll
            for (int q = 0; q < 2; q++) {
                float gv = accg[mf][nf][q],     uv = accu[mf][nf][q];
                float h  = gv / (1.f + __expf(-gv)) * uv * p0;
                __nv_bfloat16 hi = __float2bfloat16(h);
                sH[r0 * 64 + col + q] = hi;
                sL[r0 * 64 + col + q] = __float2bfloat16(h - __bfloat162float(hi));
                gv = accg[mf][nf][2 + q];  uv = accu[mf][nf][2 + q];
                h  = gv / (1.f + __expf(-gv)) * uv * p1;
                hi = __float2bfloat16(h);
                sH[r1 * 64 + col + q] = hi;
                sL[r1 * 64 + col + q] = __float2bfloat16(h - __bfloat162float(hi));
            }
        }
    }
    __syncthreads();
    for (int i = tid; i < 128 * 8; i += 256) {
        const int row = i >> 3, chunk = i & 7;
        const int m = m0 + row;
        if (m >= cnt) continue;
        const size_t off = ((size_t)e * T_TOK + m) * II + n0 + chunk * 8;
        *(uint4*)(g_Hhi + off) = *(const uint4*)(sH + row * 64 + chunk * 8);
        *(uint4*)(g_Hlo + off) = *(const uint4*)(sL + row * 64 + chunk * 8);
    }
}

// ---------------------------------------------------------------------------
// 4) GEMM2: Yp = H @ Wd^T  (K=1408), 128x128 tile, 8 warps (2x4)
// ---------------------------------------------------------------------------
__global__ __launch_bounds__(256) void gemm2_mma()
{
    extern __shared__ char smem[];
    const int e   = blockIdx.z;
    const int cnt = g_count[e];
    const int m0  = blockIdx.y * 128;
    if (m0 >= cnt) return;
    const int n0  = blockIdx.x * 128;
    const int tid = threadIdx.x;
    const int wid = tid >> 5, lane = tid & 31;
    const int warp_m = wid & 1;
    const int warp_n = wid >> 1;

    const uint32_t sd = smem_u32(smem + 1024);
    constexpr int K = II;
    constexpr int NK = K / 32;

    const size_t wb = (size_t)e * DD * II + (size_t)n0 * II;
    const __nv_bfloat16* Bh_ptr = g_Wdh + wb;
    const __nv_bfloat16* Bl_ptr = g_Wdl + wb;

    auto load_stage = [&](int buf, int kt) {
        const int k0 = kt * 32;
        const uint32_t sbase = sd + buf * G2_STAGE;
        #pragma unroll
        for (int i = 0; i < 8; i++) {
            const int idx = tid + 256 * i;
            const int mat = idx >> 9;
            const int c   = idx & 511;
            const int row = c >> 2, kc = c & 3;
            const uint32_t dst = sbase + mat * MAT_A_B + row * ROW_B + kc * 16;
            const __nv_bfloat16* src;
            if (mat < 2) {
                int r = m0 + row; if (r >= cnt) r = cnt - 1;
                src = (mat == 0 ? g_Hhi : g_Hlo) + ((size_t)e * T_TOK + r) * K + k0 + kc * 8;
            } else {
                src = (mat == 2 ? Bh_ptr : Bl_ptr) + (size_t)row * K + k0 + kc * 8;
            }
            CP_ASYNC16(dst, src);
        }
    };

    float acc[4][4][4] = {};
    load_stage(0, 0);
    CP_COMMIT();
    int buf = 0;

    for (int kt = 0; kt < NK; kt++) {
        if (kt + 1 < NK) {
            load_stage(buf ^ 1, kt + 1);
            CP_COMMIT();
            CP_WAIT1();
        } else {
            CP_WAIT0();
        }
        __syncthreads();

        const uint32_t ah_b = sd + buf * G2_STAGE + 0 * MAT_A_B;
        const uint32_t al_b = sd + buf * G2_STAGE + 1 * MAT_A_B;
        const uint32_t bh_b = sd + buf * G2_STAGE + 2 * MAT_A_B;
        const uint32_t bl_b = sd + buf * G2_STAGE + 3 * MAT_A_B;

        #pragma unroll
        for (int k16 = 0; k16 < 2; k16++) {
            uint32_t ah[4][4], al[4][4], bh[4][2], bl[4][2];
            const uint32_t acol = (k16 * 16 + (lane >> 4) * 8) * 2;
            #pragma unroll
            for (int mf = 0; mf < 4; mf++) {
                const uint32_t ao = (warp_m * 64 + mf * 16 + (lane & 15)) * ROW_B + acol;
                LDSM_X4(ah[mf][0], ah[mf][1], ah[mf][2], ah[mf][3], ah_b + ao);
                LDSM_X4(al[mf][0], al[mf][1], al[mf][2], al[mf][3], al_b + ao);
            }
            const uint32_t bcol = (k16 * 16 + ((lane >> 3) & 1) * 8) * 2;
            #pragma unroll
            for (int nh = 0; nh < 2; nh++) {
                const uint32_t bo = (warp_n * 32 + nh * 16 + (lane >> 4) * 8 + (lane & 7)) * ROW_B + bcol;
                uint32_t r0, r1, r2, r3;
                LDSM_X4(r0, r1, r2, r3, bh_b + bo);
                bh[nh*2][0]=r0; bh[nh*2][1]=r1; bh[nh*2+1][0]=r2; bh[nh*2+1][1]=r3;
                LDSM_X4(r0, r1, r2, r3, bl_b + bo);
                bl[nh*2][0]=r0; bl[nh*2][1]=r1; bl[nh*2+1][0]=r2; bl[nh*2+1][1]=r3;
            }
            #pragma unroll
            for (int mf = 0; mf < 4; mf++) {
                #pragma unroll
                for (int nf = 0; nf < 4; nf++) {
                    MMA16816(acc[mf][nf], ah[mf], bh[nf]);
                    MMA16816(acc[mf][nf], ah[mf], bl[nf]);
                    MMA16816(acc[mf][nf], al[mf], bh[nf]);
                }
            }
        }
        __syncthreads();
        buf ^= 1;
    }

    float* Cp = g_Yp + (size_t)e * T_TOK * DD;
    #pragma unroll
    for (int mf = 0; mf < 4; mf++) {
        const int r0 = m0 + warp_m * 64 + mf * 16 + (lane >> 2);
        #pragma unroll
        for (int nf = 0; nf < 4; nf++) {
            const int col = n0 + warp_n * 32 + nf * 8 + (lane & 3) * 2;
            if (r0 < cnt)
                *(float2*)(Cp + (size_t)r0 * DD + col) =
                    make_float2(acc[mf][nf][0], acc[mf][nf][1]);
            if (r0 + 8 < cnt)
                *(float2*)(Cp + (size_t)(r0 + 8) * DD + col) =
                    make_float2(acc[mf][nf][2], acc[mf][nf][3]);
        }
    }
}

// ---------------------------------------------------------------------------
// 5) combine
// ---------------------------------------------------------------------------
__global__ __launch_bounds__(256) void combine_kernel(float* __restrict__ out)
{
    const int t = blockIdx.x;
    const int4 r = g_rec[t];
    const float4* a = (const float4*)(g_Yp + ((size_t)r.x * T_TOK + r.y) * DD);
    const float4* b = (const float4*)(g_Yp + ((size_t)r.z * T_TOK + r.w) * DD);
    float4* o = (float4*)(out + (size_t)t * DD);
    const int j = threadIdx.x;
    float4 va = a[j], vb = b[j];
    o[j] = make_float4(va.x + vb.x, va.y + vb.y, va.z + vb.z, va.w + vb.w);
}

// ---------------------------------------------------------------------------
// launch
// ---------------------------------------------------------------------------
extern "C" void kernel_launch(void* const* d_in, const int* in_sizes, int n_in,
                              void* d_out, int out_size)
{
    (void)in_sizes; (void)n_in; (void)out_size;
    const float* x  = (const float*)d_in[0];
    const float* gw = (const float*)d_in[1];
    const float* wg = (const float*)d_in[2];
    const float* wu = (const float*)d_in[3];
    const float* wd = (const float*)d_in[4];
    float* out = (float*)d_out;

    cudaFuncSetAttribute(gemm1_fused, cudaFuncAttributeMaxDynamicSharedMemorySize, G1_SMEM);
    cudaFuncSetAttribute(gemm2_mma,   cudaFuncAttributeMaxDynamicSharedMemorySize, G2_SMEM);

    const int nx4 = T_TOK * DD / 4;
    const int nw4 = EE * II * DD / 4;

    zero_counts_kernel<<<1, 32>>>();
    router_kernel<<<T_TOK, 256>>>(x, gw);
    split_kernel<<<(nx4 + 255) / 256, 256>>>(x,  0, nx4);
    split_kernel<<<(nw4 + 255) / 256, 256>>>(wg, 1, nw4);
    split_kernel<<<(nw4 + 255) / 256, 256>>>(wu, 2, nw4);
    split_kernel<<<(nw4 + 255) / 256, 256>>>(wd, 3, nw4);
    gemm1_fused<<<dim3(II / 64, T_TOK / 128, EE), 256, G1_SMEM>>>();
    gemm2_mma<<<dim3(DD / 128, T_TOK / 128, EE), 256, G2_SMEM>>>();
    combine_kernel<<<T_TOK, 256>>>(out);
}

// round 7
// speedup vs baseline: 1.1037x; 1.1037x over previous
#include <cuda_runtime.h>
#include <cuda_bf16.h>
#include <cstdint>

#define T_TOK 4096   // B*S
#define DD    1024   // model dim
#define EE    8      // experts
#define II    1408   // ffn dim

// ---------------------------------------------------------------------------
// Static device scratch
// ---------------------------------------------------------------------------
__device__ int   g_count[EE];
__device__ int   g_tok [EE * T_TOK];
__device__ float g_prob[EE * T_TOK];
__device__ int4  g_rec [T_TOK];
__device__ __align__(16) __nv_bfloat16 g_Xhi[(size_t)T_TOK * DD];
__device__ __align__(16) __nv_bfloat16 g_Xlo[(size_t)T_TOK * DD];
__device__ __align__(16) __nv_bfloat16 g_Wgh[(size_t)EE * II * DD];
__device__ __align__(16) __nv_bfloat16 g_Wgl[(size_t)EE * II * DD];
__device__ __align__(16) __nv_bfloat16 g_Wuh[(size_t)EE * II * DD];
__device__ __align__(16) __nv_bfloat16 g_Wul[(size_t)EE * II * DD];
__device__ __align__(16) __nv_bfloat16 g_Wdh[(size_t)EE * DD * II];
__device__ __align__(16) __nv_bfloat16 g_Wdl[(size_t)EE * DD * II];
__device__ __align__(16) float         g_G  [(size_t)EE * T_TOK * II];
__device__ __align__(16) __nv_bfloat16 g_Hhi[(size_t)EE * T_TOK * II];
__device__ __align__(16) __nv_bfloat16 g_Hlo[(size_t)EE * T_TOK * II];
__device__ __align__(16) float         g_Yp [(size_t)EE * T_TOK * DD];

// ---------------------------------------------------------------------------
// PTX helpers (sm_80-era ISA: compiles under plain compute_100 target)
// ---------------------------------------------------------------------------
__device__ __forceinline__ uint32_t smem_u32(const void* p) {
    uint32_t a;
    asm("{ .reg .u64 t; cvta.to.shared.u64 t, %1; cvt.u32.u64 %0, t; }" : "=r"(a) : "l"(p));
    return a;
}

#define CP_ASYNC16(dst, src) \
    asm volatile("cp.async.cg.shared.global [%0], [%1], 16;" :: "r"(dst), "l"(src))
#define CP_COMMIT() asm volatile("cp.async.commit_group;")
#define CP_WAIT0()  asm volatile("cp.async.wait_group 0;")
#define CP_WAIT1()  asm volatile("cp.async.wait_group 1;")

#define LDSM_X4(r0, r1, r2, r3, addr) \
    asm volatile("ldmatrix.sync.aligned.m8n8.x4.shared.b16 {%0,%1,%2,%3}, [%4];" \
        : "=r"(r0), "=r"(r1), "=r"(r2), "=r"(r3) : "r"(addr))

#define MMA16816(d, a, b) \
    asm volatile("mma.sync.aligned.m16n8k16.row.col.f32.bf16.bf16.f32 " \
        "{%0,%1,%2,%3}, {%4,%5,%6,%7}, {%8,%9}, {%0,%1,%2,%3};" \
        : "+f"((d)[0]), "+f"((d)[1]), "+f"((d)[2]), "+f"((d)[3]) \
        : "r"((a)[0]), "r"((a)[1]), "r"((a)[2]), "r"((a)[3]), "r"((b)[0]), "r"((b)[1]))

// 80B-padded rows -> conflict-free ldmatrix
#define ROW_B   80
#define MAT_B   (128 * ROW_B)     // 10240 B per 128x32 bf16 matrix
#define STAGE_B (4 * MAT_B)       // Ahi, Alo, Bhi, Blo
#define SMEM_BYTES (1024 + 2 * STAGE_B)   // 82944

#define M_GATE 0
#define M_UP   1
#define M_DOWN 2

// ---------------------------------------------------------------------------
// 0) reset counters
// ---------------------------------------------------------------------------
__global__ void zero_counts_kernel() {
    if (threadIdx.x < EE) g_count[threadIdx.x] = 0;
}

// ---------------------------------------------------------------------------
// 1) router (verified at 1.15e-6)
// ---------------------------------------------------------------------------
__global__ __launch_bounds__(256) void router_kernel(
    const float* __restrict__ x, const float* __restrict__ gate_w)
{
    __shared__ float sx[DD];
    __shared__ float sc[EE];
    const int t = blockIdx.x, tid = threadIdx.x;
    ((float4*)sx)[tid] = ((const float4*)(x + (size_t)t * DD))[tid];
    __syncthreads();
    const int w = tid >> 5, lane = tid & 31;
    const float* gw = gate_w + w * DD;
    float s = 0.f;
    #pragma unroll 8
    for (int j = lane; j < DD; j += 32) s += sx[j] * gw[j];
    #pragma unroll
    for (int o = 16; o > 0; o >>= 1) s += __shfl_down_sync(0xFFFFFFFFu, s, o);
    if (lane == 0) sc[w] = s;
    __syncthreads();
    if (tid == 0) {
        int e0 = 0; float s0 = sc[0];
        #pragma unroll
        for (int e = 1; e < EE; e++) if (sc[e] > s0) { s0 = sc[e]; e0 = e; }
        int e1 = -1; float s1 = -3.0e38f;
        #pragma unroll
        for (int e = 0; e < EE; e++) if (e != e0 && sc[e] > s1) { s1 = sc[e]; e1 = e; }
        float z = expf(s1 - s0);
        float p1 = z / (1.f + z);
        float p0 = 1.f - p1;
        int sl0 = atomicAdd(&g_count[e0], 1);
        int sl1 = atomicAdd(&g_count[e1], 1);
        g_tok [e0 * T_TOK + sl0] = t;  g_prob[e0 * T_TOK + sl0] = p0;
        g_tok [e1 * T_TOK + sl1] = t;  g_prob[e1 * T_TOK + sl1] = p1;
        g_rec[t] = make_int4(e0, sl0, e1, sl1);
    }
}

// ---------------------------------------------------------------------------
// 2) fp32 -> (bf16 hi, bf16 lo) split
// ---------------------------------------------------------------------------
__global__ __launch_bounds__(256) void split_kernel(const float* __restrict__ s, int which, int n4)
{
    int i = blockIdx.x * 256 + threadIdx.x;
    if (i >= n4) return;
    __nv_bfloat16 *hi, *lo;
    switch (which) {
        case 0:  hi = g_Xhi; lo = g_Xlo; break;
        case 1:  hi = g_Wgh; lo = g_Wgl; break;
        case 2:  hi = g_Wuh; lo = g_Wul; break;
        default: hi = g_Wdh; lo = g_Wdl; break;
    }
    float4 v = ((const float4*)s)[i];
    float vv[4] = {v.x, v.y, v.z, v.w};
    unsigned short h[4], l[4];
    #pragma unroll
    for (int j = 0; j < 4; j++) {
        __nv_bfloat16 a = __float2bfloat16(vv[j]);
        __nv_bfloat16 b = __float2bfloat16(vv[j] - __bfloat162float(a));
        h[j] = __bfloat16_as_ushort(a);
        l[j] = __bfloat16_as_ushort(b);
    }
    *(ushort4*)(hi + 4 * (size_t)i) = make_ushort4(h[0], h[1], h[2], h[3]);
    *(ushort4*)(lo + 4 * (size_t)i) = make_ushort4(l[0], l[1], l[2], l[3]);
}

// ---------------------------------------------------------------------------
// 3) bf16x3 mma.sync GEMM, 128x128x32 tile, 8 warps (2x4), 2-stage cp.async.
//    M_GATE: G  = Xe @ Wg^T              (K=1024, N=1408) -> fp32
//    M_UP  : u  = Xe @ Wu^T; epilogue reads G, writes H = silu(g)*u*p (bf16 hi/lo)
//    M_DOWN: Yp = H  @ Wd^T              (K=1408, N=1024) -> fp32
// ---------------------------------------------------------------------------
template<int MODE>
__global__ __launch_bounds__(256) void gemm_mma()
{
    extern __shared__ char smem[];
    const int e   = blockIdx.z;
    const int cnt = g_count[e];
    const int m0  = blockIdx.y * 128;
    if (m0 >= cnt) return;
    const int n0  = blockIdx.x * 128;
    const int tid = threadIdx.x;
    const int wid = tid >> 5, lane = tid & 31;
    const int warp_m = wid & 1;   // 0..1  (64 rows each)
    const int warp_n = wid >> 1;  // 0..3  (32 cols each)

    int* s_tok = (int*)smem;
    const uint32_t sd = smem_u32(smem + 1024);

    if (MODE != M_DOWN && tid < 128) {
        int m = m0 + tid;
        s_tok[tid] = g_tok[e * T_TOK + (m < cnt ? m : cnt - 1)];
    }
    __syncthreads();

    constexpr int K  = (MODE == M_DOWN) ? II : DD;
    constexpr int NK = K / 32;

    const __nv_bfloat16* Ah_base = (MODE == M_DOWN) ? g_Hhi : g_Xhi;
    const __nv_bfloat16* Al_base = (MODE == M_DOWN) ? g_Hlo : g_Xlo;
    const __nv_bfloat16* Bh_ptr;
    const __nv_bfloat16* Bl_ptr;
    if (MODE == M_GATE) {
        const size_t wb = (size_t)e * II * DD + (size_t)n0 * DD;
        Bh_ptr = g_Wgh + wb;  Bl_ptr = g_Wgl + wb;
    } else if (MODE == M_UP) {
        const size_t wb = (size_t)e * II * DD + (size_t)n0 * DD;
        Bh_ptr = g_Wuh + wb;  Bl_ptr = g_Wul + wb;
    } else {
        const size_t wb = (size_t)e * DD * II + (size_t)n0 * II;
        Bh_ptr = g_Wdh + wb;  Bl_ptr = g_Wdl + wb;
    }

    auto load_stage = [&](int buf, int kt) {
        const int k0 = kt * 32;
        const uint32_t sbase = sd + buf * STAGE_B;
        #pragma unroll
        for (int i = 0; i < 8; i++) {
            const int idx = tid + 256 * i;
            const int mat = idx >> 9;          // 0:Ahi 1:Alo 2:Bhi 3:Blo
            const int c   = idx & 511;
            const int row = c >> 2;
            const int kc  = c & 3;
            const uint32_t dst = sbase + mat * MAT_B + row * ROW_B + kc * 16;
            const __nv_bfloat16* src;
            if (mat < 2) {
                size_t grow;
                if (MODE != M_DOWN) grow = (size_t)s_tok[row];
                else {
                    int r = m0 + row; if (r >= cnt) r = cnt - 1;
                    grow = (size_t)e * T_TOK + r;
                }
                src = (mat == 0 ? Ah_base : Al_base) + grow * (size_t)K + k0 + kc * 8;
            } else {
                src = (mat == 2 ? Bh_ptr : Bl_ptr) + (size_t)row * K + k0 + kc * 8;
            }
            CP_ASYNC16(dst, src);
        }
    };

    float acc[4][4][4] = {};

    load_stage(0, 0);
    CP_COMMIT();
    int buf = 0;

    for (int kt = 0; kt < NK; kt++) {
        if (kt + 1 < NK) {
            load_stage(buf ^ 1, kt + 1);
            CP_COMMIT();
            CP_WAIT1();
        } else {
            CP_WAIT0();
        }
        __syncthreads();

        const uint32_t ah_b = sd + buf * STAGE_B + 0 * MAT_B;
        const uint32_t al_b = sd + buf * STAGE_B + 1 * MAT_B;
        const uint32_t bh_b = sd + buf * STAGE_B + 2 * MAT_B;
        const uint32_t bl_b = sd + buf * STAGE_B + 3 * MAT_B;

        #pragma unroll
        for (int k16 = 0; k16 < 2; k16++) {
            uint32_t ah[4][4], al[4][4], bh[4][2], bl[4][2];
            const uint32_t acol = (k16 * 16 + (lane >> 4) * 8) * 2;
            #pragma unroll
            for (int mf = 0; mf < 4; mf++) {
                const uint32_t ao = (warp_m * 64 + mf * 16 + (lane & 15)) * ROW_B + acol;
                LDSM_X4(ah[mf][0], ah[mf][1], ah[mf][2], ah[mf][3], ah_b + ao);
                LDSM_X4(al[mf][0], al[mf][1], al[mf][2], al[mf][3], al_b + ao);
            }
            const uint32_t bcol = (k16 * 16 + ((lane >> 3) & 1) * 8) * 2;
            #pragma unroll
            for (int nh = 0; nh < 2; nh++) {
                const uint32_t bo = (warp_n * 32 + nh * 16 + (lane >> 4) * 8 + (lane & 7)) * ROW_B + bcol;
                uint32_t r0, r1, r2, r3;
                LDSM_X4(r0, r1, r2, r3, bh_b + bo);
                bh[nh * 2][0] = r0; bh[nh * 2][1] = r1;
                bh[nh * 2 + 1][0] = r2; bh[nh * 2 + 1][1] = r3;
                LDSM_X4(r0, r1, r2, r3, bl_b + bo);
                bl[nh * 2][0] = r0; bl[nh * 2][1] = r1;
                bl[nh * 2 + 1][0] = r2; bl[nh * 2 + 1][1] = r3;
            }
            #pragma unroll
            for (int mf = 0; mf < 4; mf++) {
                #pragma unroll
                for (int nf = 0; nf < 4; nf++) {
                    MMA16816(acc[mf][nf], ah[mf], bh[nf]);
                    MMA16816(acc[mf][nf], ah[mf], bl[nf]);
                    MMA16816(acc[mf][nf], al[mf], bh[nf]);
                }
            }
        }
        __syncthreads();
        buf ^= 1;
    }

    // ---- epilogue ---------------------------------------------------------
    if (MODE == M_GATE) {
        float* Cp = g_G + (size_t)e * T_TOK * II;
        #pragma unroll
        for (int mf = 0; mf < 4; mf++) {
            const int r0 = m0 + warp_m * 64 + mf * 16 + (lane >> 2);
            #pragma unroll
            for (int nf = 0; nf < 4; nf++) {
                const int col = n0 + warp_n * 32 + nf * 8 + (lane & 3) * 2;
                if (r0 < cnt)
                    *(float2*)(Cp + (size_t)r0 * II + col) =
                        make_float2(acc[mf][nf][0], acc[mf][nf][1]);
                if (r0 + 8 < cnt)
                    *(float2*)(Cp + (size_t)(r0 + 8) * II + col) =
                        make_float2(acc[mf][nf][2], acc[mf][nf][3]);
            }
        }
    } else if (MODE == M_UP) {
        const float* Gp = g_G + (size_t)e * T_TOK * II;
        #pragma unroll
        for (int mf = 0; mf < 4; mf++) {
            const int r0 = m0 + warp_m * 64 + mf * 16 + (lane >> 2);
            const int r1 = r0 + 8;
            const float p0 = (r0 < cnt) ? g_prob[e * T_TOK + r0] : 0.f;
            const float p1 = (r1 < cnt) ? g_prob[e * T_TOK + r1] : 0.f;
            #pragma unroll
            for (int nf = 0; nf < 4; nf++) {
                const int col = n0 + warp_n * 32 + nf * 8 + (lane & 3) * 2;
                if (r0 < cnt) {
                    float2 gv = *(const float2*)(Gp + (size_t)r0 * II + col);
                    float h0 = gv.x / (1.f + __expf(-gv.x)) * acc[mf][nf][0] * p0;
                    float h1 = gv.y / (1.f + __expf(-gv.y)) * acc[mf][nf][1] * p0;
                    __nv_bfloat16 hi0 = __float2bfloat16(h0);
                    __nv_bfloat16 hi1 = __float2bfloat16(h1);
                    const size_t off = ((size_t)e * T_TOK + r0) * II + col;
                    *(ushort2*)(g_Hhi + off) = make_ushort2(
                        __bfloat16_as_ushort(hi0), __bfloat16_as_ushort(hi1));
                    *(ushort2*)(g_Hlo + off) = make_ushort2(
                        __bfloat16_as_ushort(__float2bfloat16(h0 - __bfloat162float(hi0))),
                        __bfloat16_as_ushort(__float2bfloat16(h1 - __bfloat162float(hi1))));
                }
                if (r1 < cnt) {
                    float2 gv = *(const float2*)(Gp + (size_t)r1 * II + col);
                    float h0 = gv.x / (1.f + __expf(-gv.x)) * acc[mf][nf][2] * p1;
                    float h1 = gv.y / (1.f + __expf(-gv.y)) * acc[mf][nf][3] * p1;
                    __nv_bfloat16 hi0 = __float2bfloat16(h0);
                    __nv_bfloat16 hi1 = __float2bfloat16(h1);
                    const size_t off = ((size_t)e * T_TOK + r1) * II + col;
                    *(ushort2*)(g_Hhi + off) = make_ushort2(
                        __bfloat16_as_ushort(hi0), __bfloat16_as_ushort(hi1));
                    *(ushort2*)(g_Hlo + off) = make_ushort2(
                        __bfloat16_as_ushort(__float2bfloat16(h0 - __bfloat162float(hi0))),
                        __bfloat16_as_ushort(__float2bfloat16(h1 - __bfloat162float(hi1))));
                }
            }
        }
    } else {
        float* Cp = g_Yp + (size_t)e * T_TOK * DD;
        #pragma unroll
        for (int mf = 0; mf < 4; mf++) {
            const int r0 = m0 + warp_m * 64 + mf * 16 + (lane >> 2);
            #pragma unroll
            for (int nf = 0; nf < 4; nf++) {
                const int col = n0 + warp_n * 32 + nf * 8 + (lane & 3) * 2;
                if (r0 < cnt)
                    *(float2*)(Cp + (size_t)r0 * DD + col) =
                        make_float2(acc[mf][nf][0], acc[mf][nf][1]);
                if (r0 + 8 < cnt)
                    *(float2*)(Cp + (size_t)(r0 + 8) * DD + col) =
                        make_float2(acc[mf][nf][2], acc[mf][nf][3]);
            }
        }
    }
}

// ---------------------------------------------------------------------------
// 4) combine
// ---------------------------------------------------------------------------
__global__ __launch_bounds__(256) void combine_kernel(float* __restrict__ out)
{
    const int t = blockIdx.x;
    const int4 r = g_rec[t];
    const float4* a = (const float4*)(g_Yp + ((size_t)r.x * T_TOK + r.y) * DD);
    const float4* b = (const float4*)(g_Yp + ((size_t)r.z * T_TOK + r.w) * DD);
    float4* o = (float4*)(out + (size_t)t * DD);
    const int j = threadIdx.x;
    float4 va = a[j], vb = b[j];
    o[j] = make_float4(va.x + vb.x, va.y + vb.y, va.z + vb.z, va.w + vb.w);
}

// ---------------------------------------------------------------------------
// launch
// ---------------------------------------------------------------------------
extern "C" void kernel_launch(void* const* d_in, const int* in_sizes, int n_in,
                              void* d_out, int out_size)
{
    (void)in_sizes; (void)n_in; (void)out_size;
    const float* x  = (const float*)d_in[0];
    const float* gw = (const float*)d_in[1];
    const float* wg = (const float*)d_in[2];
    const float* wu = (const float*)d_in[3];
    const float* wd = (const float*)d_in[4];
    float* out = (float*)d_out;

    cudaFuncSetAttribute(gemm_mma<M_GATE>, cudaFuncAttributeMaxDynamicSharedMemorySize, SMEM_BYTES);
    cudaFuncSetAttribute(gemm_mma<M_UP>,   cudaFuncAttributeMaxDynamicSharedMemorySize, SMEM_BYTES);
    cudaFuncSetAttribute(gemm_mma<M_DOWN>, cudaFuncAttributeMaxDynamicSharedMemorySize, SMEM_BYTES);

    const int nx4 = T_TOK * DD / 4;
    const int nw4 = EE * II * DD / 4;

    zero_counts_kernel<<<1, 32>>>();
    router_kernel<<<T_TOK, 256>>>(x, gw);
    split_kernel<<<(nx4 + 255) / 256, 256>>>(x,  0, nx4);
    split_kernel<<<(nw4 + 255) / 256, 256>>>(wg, 1, nw4);
    split_kernel<<<(nw4 + 255) / 256, 256>>>(wu, 2, nw4);
    split_kernel<<<(nw4 + 255) / 256, 256>>>(wd, 3, nw4);
    gemm_mma<M_GATE><<<dim3(II / 128, T_TOK / 128, EE), 256, SMEM_BYTES>>>();
    gemm_mma<M_UP>  <<<dim3(II / 128, T_TOK / 128, EE), 256, SMEM_BYTES>>>();
    gemm_mma<M_DOWN><<<dim3(DD / 128, T_TOK / 128, EE), 256, SMEM_BYTES>>>();
    combine_kernel<<<T_TOK, 256>>>(out);
}